// round 9
// baseline (speedup 1.0000x reference)
#include <cuda_runtime.h>
#include <cuda_bf16.h>
#include <cuda_fp16.h>
#include <math.h>
#include <stdint.h>

#define N_NODES 100000
#define N_EDGES 1600000
#define NCLASS  40
#define LALPHA  0.2f
#define FULLMASK 0xffffffffu

// ---------------- scratch (static device globals) ----------------
__device__ __align__(16) __half g_W1t_hi[256 * 256];           // Wcat^T fp16 hi
__device__ __align__(16) __half g_W1t_lo[256 * 256];           // Wcat^T fp16 lo (residual)
__device__ __align__(16) __half g_W2f[64 * 256];               // W_out^T padded, fp16
__device__ __align__(16) __half g_Wh1f[(size_t)N_NODES * 256]; // layer1 features fp16
__device__ __align__(16) __half g_Xf[(size_t)N_NODES * 256];   // layer1 output fp16
__device__ __align__(16) __half g_Wh2f[(size_t)N_NODES * 40];  // layer2 logits fp16, stride 40
__device__ float4 g_s1src[N_NODES];
__device__ float4 g_s1dst[N_NODES];
__device__ float g_s2src[N_NODES];
__device__ float g_s2dst[N_NODES];
__device__ int g_deg[N_NODES + 1];
__device__ int g_off[N_NODES + 1];
__device__ int g_rank[N_EDGES];
__device__ int g_eid[N_EDGES];
__device__ int g_bsum[128];
__device__ int g_bsum2[128];
__device__ unsigned g_gmax[10];

// ---------------- helpers ----------------
__device__ __forceinline__ float wredmax(float v) {
#pragma unroll
    for (int o = 16; o; o >>= 1) v = fmaxf(v, __shfl_xor_sync(FULLMASK, v, o));
    return v;
}
__device__ __forceinline__ float wredsum(float v) {
#pragma unroll
    for (int o = 16; o; o >>= 1) v += __shfl_xor_sync(FULLMASK, v, o);
    return v;
}
__device__ __forceinline__ float lrelu(float x) { return x > 0.f ? x : LALPHA * x; }
__device__ __forceinline__ unsigned encf(float f) {
    int i = __float_as_int(f);
    return (i < 0) ? ~(unsigned)i : ((unsigned)i | 0x80000000u);
}
__device__ __forceinline__ float decf(unsigned u) {
    int i = (u & 0x80000000u) ? (int)(u & 0x7fffffffu) : ~(int)u;
    return __int_as_float(i);
}
__device__ __forceinline__ void mma_f16(float* c, const unsigned* a, const unsigned* b) {
    asm volatile(
        "mma.sync.aligned.m16n8k16.row.col.f32.f16.f16.f32 "
        "{%0,%1,%2,%3},{%4,%5,%6,%7},{%8,%9},{%0,%1,%2,%3};"
        : "+f"(c[0]), "+f"(c[1]), "+f"(c[2]), "+f"(c[3])
        : "r"(a[0]), "r"(a[1]), "r"(a[2]), "r"(a[3]), "r"(b[0]), "r"(b[1]));
}
__device__ __forceinline__ void ldsm_x4(unsigned* r, unsigned a) {
    asm volatile("ldmatrix.sync.aligned.m8n8.x4.shared.b16 {%0,%1,%2,%3}, [%4];"
                 : "=r"(r[0]), "=r"(r[1]), "=r"(r[2]), "=r"(r[3]) : "r"(a));
}
__device__ __forceinline__ void cp16(unsigned d, const void* s, int sz) {
    asm volatile("cp.async.cg.shared.global [%0], [%1], 16, %2;" :: "r"(d), "l"(s), "r"(sz));
}
__device__ __forceinline__ void cp_commit() { asm volatile("cp.async.commit_group;"); }
template <int NW> __device__ __forceinline__ void cp_wait() {
    asm volatile("cp.async.wait_group %0;" :: "n"(NW));
}

// ---------------- merged setup: pack W1 fp16 hi/lo, pack W2, zero deg/gmax ----------------
__global__ void setup_kernel(const float* __restrict__ Wh, const float* __restrict__ Wo) {
    int idx = blockIdx.x * blockDim.x + threadIdx.x;
    if (idx <= N_NODES) g_deg[idx] = 0;
    if (idx < 10) g_gmax[idx] = encf(-3e38f);
    if (idx < 256 * 256) {
        int c = idx >> 8, k = idx & 255;
        int head = c >> 6, j = c & 63;
        float v = Wh[head * (256 * 64) + k * 64 + j];
        __half hi = __float2half_rn(v);
        g_W1t_hi[c * 256 + k] = hi;
        g_W1t_lo[c * 256 + k] = __float2half_rn(v - __half2float(hi));
    }
    if (idx < 64 * 256) {
        int c = idx >> 8, k = idx & 255;
        float v = (c < NCLASS) ? Wo[k * NCLASS + c] : 0.f;
        g_W2f[c * 256 + k] = __float2half_rn(v);
    }
}

// ---------------- GEMM1: Wh1 = h @ Wcat, A fp32 staged -> fp16 in-kernel; 2-term fp16 mma ----
__global__ __launch_bounds__(256, 2) void gemm1_kernel(
    const float* __restrict__ A,
    const __half* __restrict__ Bth, const __half* __restrict__ Btl,
    __half* __restrict__ Whf, const float* __restrict__ a_heads, int M) {
    constexpr int MI = 4, NI = 4;
    constexpr int LDSB = 40;
    constexpr int LDSAF = 36;
    constexpr int SZAF = 64 * LDSAF * 4;
    constexpr int OFF_AH = 2 * SZAF;
    constexpr int OFF_B = OFF_AH + 64 * LDSB * 2;
    constexpr int SZB = 256 * LDSB * 2;

    extern __shared__ char smem[];
    const unsigned uS = (unsigned)__cvta_generic_to_shared(smem);
    const unsigned uAf = uS;
    const unsigned uAh = uS + OFF_AH;
    const unsigned uBh = uS + OFF_B;
    const unsigned uBl = uS + OFF_B + 2 * SZB;
    float* sP = (float*)smem;
    float* sQ = (float*)(smem + 2048);
    float* sMp = (float*)(smem + 4096);
    float* sMq = (float*)(smem + 4224);

    const int tid = threadIdx.x, lane = tid & 31, wid = tid >> 5;
    const int wn = wid;
    const int brow = blockIdx.y * 64;

    float acc[MI][NI][4];
#pragma unroll
    for (int mi = 0; mi < MI; mi++)
#pragma unroll
        for (int ni = 0; ni < NI; ni++)
#pragma unroll
            for (int q = 0; q < 4; q++) acc[mi][ni][q] = 0.f;

    auto stage = [&](int s, int k0) {
#pragma unroll
        for (int it = 0; it < 2; it++) {
            int i = tid + it * 256;
            int row = i >> 3, c = i & 7;
            int gr = brow + row;
            int ok = (gr < M) ? 16 : 0;
            const float* srcp = A + (size_t)min(gr, M - 1) * 256 + k0 + c * 4;
            cp16(uAf + (unsigned)(s * SZAF + (row * LDSAF + c * 4) * 4), srcp, ok);
        }
#pragma unroll
        for (int it = 0; it < 4; it++) {
            int i = tid + it * 256;
            int row = i >> 2, c = i & 3;
            size_t go = (size_t)row * 256 + k0 + c * 8;
            unsigned dof = (unsigned)(s * SZB + (row * LDSB + c * 8) * 2);
            cp16(uBh + dof, Bth + go, 16);
            cp16(uBl + dof, Btl + go, 16);
        }
    };

    stage(0, 0);
    cp_commit();

#pragma unroll
    for (int it = 0; it < 8; it++) {
        const int s = it & 1;
        if (it < 7) {
            stage(s ^ 1, (it + 1) * 32);
            cp_commit();
            cp_wait<1>();
        } else {
            cp_wait<0>();
        }
        __syncthreads();

        {
            int row = tid >> 2, seg = tid & 3;
            const char* pf = smem + s * SZAF + (row * LDSAF + seg * 8) * 4;
            float4 v0 = *(const float4*)pf;
            float4 v1 = *(const float4*)(pf + 16);
            __half hh[8];
            hh[0] = __float2half_rn(v0.x); hh[1] = __float2half_rn(v0.y);
            hh[2] = __float2half_rn(v0.z); hh[3] = __float2half_rn(v0.w);
            hh[4] = __float2half_rn(v1.x); hh[5] = __float2half_rn(v1.y);
            hh[6] = __float2half_rn(v1.z); hh[7] = __float2half_rn(v1.w);
            *(uint4*)(smem + OFF_AH + (row * LDSB + seg * 8) * 2) = *(uint4*)hh;
        }
        __syncthreads();

#pragma unroll
        for (int kk = 0; kk < 32; kk += 16) {
            unsigned ah[MI][4], bh[NI][2], bl[NI][2];
            const int ra = lane & 15;
            const int kca = (lane >> 4) << 3;
#pragma unroll
            for (int mi = 0; mi < MI; mi++) {
                unsigned off = (unsigned)(((mi * 16 + ra) * LDSB + kk + kca) * 2);
                ldsm_x4(ah[mi], uAh + off);
            }
            const int rb = (lane & 7) + ((lane >> 4) << 3);
            const int kcb = ((lane >> 3) & 1) << 3;
#pragma unroll
            for (int nb = 0; nb < NI / 2; nb++) {
                unsigned off = (unsigned)(((wn * 32 + nb * 16 + rb) * LDSB + kk + kcb) * 2) +
                               (unsigned)(s * SZB);
                unsigned t4[4];
                ldsm_x4(t4, uBh + off);
                bh[2 * nb][0] = t4[0]; bh[2 * nb][1] = t4[1];
                bh[2 * nb + 1][0] = t4[2]; bh[2 * nb + 1][1] = t4[3];
                ldsm_x4(t4, uBl + off);
                bl[2 * nb][0] = t4[0]; bl[2 * nb][1] = t4[1];
                bl[2 * nb + 1][0] = t4[2]; bl[2 * nb + 1][1] = t4[3];
            }
#pragma unroll
            for (int mi = 0; mi < MI; mi++)
#pragma unroll
                for (int ni = 0; ni < NI; ni++) {
                    mma_f16(acc[mi][ni], ah[mi], bh[ni]);
                    mma_f16(acc[mi][ni], ah[mi], bl[ni]);
                }
        }
        __syncthreads();
    }

    // epilogue: fused scores + fp16 store
    const int g = lane >> 2, t = lane & 3;
    float asr[NI][2], adr[NI][2];
#pragma unroll
    for (int ni = 0; ni < NI; ni++)
#pragma unroll
        for (int qq = 0; qq < 2; qq++) {
            int cl = wn * 32 + ni * 8 + 2 * t + qq;
            asr[ni][qq] = a_heads[(cl >> 6) * 128 + (cl & 63)];
            adr[ni][qq] = a_heads[(cl >> 6) * 128 + 64 + (cl & 63)];
        }
#pragma unroll
    for (int mi = 0; mi < MI; mi++) {
        float p0 = 0.f, q0 = 0.f, p1 = 0.f, q1 = 0.f;
#pragma unroll
        for (int ni = 0; ni < NI; ni++)
#pragma unroll
            for (int qq = 0; qq < 2; qq++) {
                p0 += acc[mi][ni][qq] * asr[ni][qq];
                q0 += acc[mi][ni][qq] * adr[ni][qq];
                p1 += acc[mi][ni][2 + qq] * asr[ni][qq];
                q1 += acc[mi][ni][2 + qq] * adr[ni][qq];
            }
#pragma unroll
        for (int o = 1; o <= 2; o <<= 1) {
            p0 += __shfl_xor_sync(FULLMASK, p0, o);
            q0 += __shfl_xor_sync(FULLMASK, q0, o);
            p1 += __shfl_xor_sync(FULLMASK, p1, o);
            q1 += __shfl_xor_sync(FULLMASK, q1, o);
        }
        int r0 = mi * 16 + g;
        if (t == 0) {
            sP[r0 * 8 + wn] = p0; sQ[r0 * 8 + wn] = q0;
            sP[(r0 + 8) * 8 + wn] = p1; sQ[(r0 + 8) * 8 + wn] = q1;
        }
        int gr0 = brow + r0;
#pragma unroll
        for (int ni = 0; ni < NI; ni++) {
            int c = wn * 32 + ni * 8 + 2 * t;
            if (gr0 < M)
                *(__half2*)(Whf + (size_t)gr0 * 256 + c) =
                    __floats2half2_rn(acc[mi][ni][0], acc[mi][ni][1]);
            if (gr0 + 8 < M)
                *(__half2*)(Whf + (size_t)(gr0 + 8) * 256 + c) =
                    __floats2half2_rn(acc[mi][ni][2], acc[mi][ni][3]);
        }
    }
    __syncthreads();
    {
        int row = tid >> 2, hd = tid & 3;
        int gr = brow + row;
        float p = -3e38f, q = -3e38f;
        float pv = sP[row * 8 + 2 * hd] + sP[row * 8 + 2 * hd + 1];
        float qv = sQ[row * 8 + 2 * hd] + sQ[row * 8 + 2 * hd + 1];
        if (gr < M) {
            ((float*)g_s1src)[gr * 4 + hd] = pv;
            ((float*)g_s1dst)[gr * 4 + hd] = qv;
            p = pv; q = qv;
        }
#pragma unroll
        for (int o = 4; o <= 16; o <<= 1) {
            p = fmaxf(p, __shfl_xor_sync(FULLMASK, p, o));
            q = fmaxf(q, __shfl_xor_sync(FULLMASK, q, o));
        }
        if (lane < 4) {
            sMp[wid * 4 + lane] = p;
            sMq[wid * 4 + lane] = q;
        }
    }
    __syncthreads();
    if (tid < 32) {
        int h = tid & 3;
        float p = sMp[tid], q = sMq[tid];
#pragma unroll
        for (int o = 4; o <= 16; o <<= 1) {
            p = fmaxf(p, __shfl_xor_sync(FULLMASK, p, o));
            q = fmaxf(q, __shfl_xor_sync(FULLMASK, q, o));
        }
        if (tid < 4) {
            atomicMax(&g_gmax[h], encf(p));
            atomicMax(&g_gmax[4 + h], encf(q));
        }
    }
}

// ---------------- GEMM2: Wh2 = x @ W2 (fp16 1-term) + fused scores2 + max (chunked rows) ----
__global__ __launch_bounds__(256, 2) void gemm2_kernel(
    const __half* __restrict__ A, const __half* __restrict__ Bt,
    __half* __restrict__ Whf, const float* __restrict__ a_out, int row0, int rowEnd) {
    constexpr int WM = 64, WN = 16, MI = 4, NI = 2, WNW = 4;
    constexpr int LDSB = 40;
    constexpr int SZA = 128 * LDSB * 2;
    constexpr int SZB = 64 * LDSB * 2;

    extern __shared__ char smem[];
    const unsigned uA = (unsigned)__cvta_generic_to_shared(smem);
    const unsigned uB = uA + 2 * SZA;
    __shared__ float sAS[64], sAD[64];
    __shared__ float sP[128][4], sQ[128][4];
    __shared__ float sMp[8], sMq[8];

    const int tid = threadIdx.x, lane = tid & 31, wid = tid >> 5;
    const int wm = wid / WNW, wn = wid % WNW;
    const int brow = row0 + blockIdx.y * 128;
    const int M = rowEnd;

    if (tid < 64) {
        sAS[tid] = (tid < NCLASS) ? a_out[tid] : 0.f;
        sAD[tid] = (tid < NCLASS) ? a_out[NCLASS + tid] : 0.f;
    }

    float acc[MI][NI][4];
#pragma unroll
    for (int mi = 0; mi < MI; mi++)
#pragma unroll
        for (int ni = 0; ni < NI; ni++)
#pragma unroll
            for (int q = 0; q < 4; q++) acc[mi][ni][q] = 0.f;

    auto stage = [&](int s, int k0) {
#pragma unroll
        for (int i = tid; i < 512; i += 256) {
            int row = i >> 2, c = i & 3;
            int gr = brow + row;
            int ok = (gr < M) ? 16 : 0;
            size_t go = (size_t)min(gr, M - 1) * 256 + k0 + c * 8;
            cp16(uA + (unsigned)(s * SZA + (row * LDSB + c * 8) * 2), A + go, ok);
        }
        if (tid < 256) {
            int row = tid >> 2, c = tid & 3;
            size_t go = (size_t)row * 256 + k0 + c * 8;
            cp16(uB + (unsigned)(s * SZB + (row * LDSB + c * 8) * 2), Bt + go, 16);
        }
    };

    stage(0, 0);
    cp_commit();

#pragma unroll
    for (int it = 0; it < 8; it++) {
        const int s = it & 1;
        if (it < 7) {
            stage(s ^ 1, (it + 1) * 32);
            cp_commit();
            cp_wait<1>();
        } else {
            cp_wait<0>();
        }
        __syncthreads();

#pragma unroll
        for (int kk = 0; kk < 32; kk += 16) {
            unsigned af[MI][4], bf[NI][2];
            const int ra = lane & 15;
            const int kca = (lane >> 4) << 3;
#pragma unroll
            for (int mi = 0; mi < MI; mi++) {
                unsigned off = (unsigned)(((wm * WM + mi * 16 + ra) * LDSB + kk + kca) * 2) +
                               (unsigned)(s * SZA);
                ldsm_x4(af[mi], uA + off);
            }
            const int rb = (lane & 7) + ((lane >> 4) << 3);
            const int kcb = ((lane >> 3) & 1) << 3;
            {
                unsigned off = (unsigned)(((wn * WN + rb) * LDSB + kk + kcb) * 2) +
                               (unsigned)(s * SZB);
                unsigned t4[4];
                ldsm_x4(t4, uB + off);
                bf[0][0] = t4[0]; bf[0][1] = t4[1];
                bf[1][0] = t4[2]; bf[1][1] = t4[3];
            }
#pragma unroll
            for (int mi = 0; mi < MI; mi++)
#pragma unroll
                for (int ni = 0; ni < NI; ni++)
                    mma_f16(acc[mi][ni], af[mi], bf[ni]);
        }
        __syncthreads();
    }

    const int g = lane >> 2, t = lane & 3;
#pragma unroll
    for (int mi = 0; mi < MI; mi++) {
        float p0 = 0.f, q0 = 0.f, p1 = 0.f, q1 = 0.f;
#pragma unroll
        for (int ni = 0; ni < NI; ni++)
#pragma unroll
            for (int qq = 0; qq < 2; qq++) {
                int cl = wn * WN + ni * 8 + 2 * t + qq;
                float as = sAS[cl], ad = sAD[cl];
                p0 += acc[mi][ni][qq] * as;
                q0 += acc[mi][ni][qq] * ad;
                p1 += acc[mi][ni][2 + qq] * as;
                q1 += acc[mi][ni][2 + qq] * ad;
            }
#pragma unroll
        for (int o = 1; o <= 2; o <<= 1) {
            p0 += __shfl_xor_sync(FULLMASK, p0, o);
            q0 += __shfl_xor_sync(FULLMASK, q0, o);
            p1 += __shfl_xor_sync(FULLMASK, p1, o);
            q1 += __shfl_xor_sync(FULLMASK, q1, o);
        }
        int r0 = wm * WM + mi * 16 + g;
        if (t == 0) {
            sP[r0][wn] = p0; sQ[r0][wn] = q0;
            sP[r0 + 8][wn] = p1; sQ[r0 + 8][wn] = q1;
        }
        int gr0 = brow + r0;
#pragma unroll
        for (int ni = 0; ni < NI; ni++) {
            int c = wn * WN + ni * 8 + 2 * t;
            if (c < NCLASS) {
                if (gr0 < M)
                    *(__half2*)(Whf + (size_t)gr0 * 40 + c) =
                        __floats2half2_rn(acc[mi][ni][0], acc[mi][ni][1]);
                if (gr0 + 8 < M)
                    *(__half2*)(Whf + (size_t)(gr0 + 8) * 40 + c) =
                        __floats2half2_rn(acc[mi][ni][2], acc[mi][ni][3]);
            }
        }
    }
    __syncthreads();
    {
        float p = -3e38f, q = -3e38f;
        if (tid < 128) {
            int gr = brow + tid;
            float pv = sP[tid][0] + sP[tid][1] + sP[tid][2] + sP[tid][3];
            float qv = sQ[tid][0] + sQ[tid][1] + sQ[tid][2] + sQ[tid][3];
            if (gr < M) {
                g_s2src[gr] = pv;
                g_s2dst[gr] = qv;
                p = pv; q = qv;
            }
        }
        p = wredmax(p);
        q = wredmax(q);
        if (lane == 0) {
            sMp[wid] = p;
            sMq[wid] = q;
        }
    }
    __syncthreads();
    if (tid == 0) {
        float p = sMp[0], q = sMq[0];
#pragma unroll
        for (int w = 1; w < 8; w++) {
            p = fmaxf(p, sMp[w]);
            q = fmaxf(q, sMq[w]);
        }
        atomicMax(&g_gmax[8], encf(p));
        atomicMax(&g_gmax[9], encf(q));
    }
}

// ---------------- CSR build (single-atomic: count stores rank) ----------------
__global__ void count_kernel(const int* __restrict__ dst) {
    int e = blockIdx.x * blockDim.x + threadIdx.x;
    if (e < N_EDGES) g_rank[e] = atomicAdd(&g_deg[dst[e]], 1);
}
__global__ void scan1_kernel(int n) {
    __shared__ int s[1024];
    int tid = threadIdx.x;
    int gid = blockIdx.x * 1024 + tid;
    int v = (gid < n) ? g_deg[gid] : 0;
    s[tid] = v;
    __syncthreads();
    int t = v;
    for (int d = 1; d < 1024; d <<= 1) {
        int add = (tid >= d) ? s[tid - d] : 0;
        __syncthreads();
        t += add;
        s[tid] = t;
        __syncthreads();
    }
    if (gid < n) g_off[gid] = t - v;
    if (tid == 1023) g_bsum[blockIdx.x] = t;
}
__global__ void scan2_kernel(int nb) {
    __shared__ int s[128];
    int tid = threadIdx.x;
    int v = (tid < nb) ? g_bsum[tid] : 0;
    s[tid] = v;
    __syncthreads();
    int t = v;
    for (int d = 1; d < 128; d <<= 1) {
        int add = (tid >= d) ? s[tid - d] : 0;
        __syncthreads();
        t += add;
        s[tid] = t;
        __syncthreads();
    }
    if (tid < nb) g_bsum2[tid] = t - v;
}
__global__ void scan3_kernel(int n) {
    int i = blockIdx.x * blockDim.x + threadIdx.x;
    if (i < n) g_off[i] += g_bsum2[i >> 10];
}
__global__ void fill_kernel(const int* __restrict__ dst, const int* __restrict__ src) {
    int e = blockIdx.x * blockDim.x + threadIdx.x;
    if (e >= N_EDGES) return;
    int pos = g_off[dst[e]] + g_rank[e];
    g_eid[pos] = src[e];
}

// ---------------- layer-1 aggregation: fp16 gather, single pass (node range) ----------------
__global__ void agg1_kernel(int node0, int node1) {
    __shared__ float4 sw[8][32];
    __shared__ int ssm[8][32];
    int gw = node0 + blockIdx.x * 8 + (threadIdx.x >> 5);
    int lane = threadIdx.x & 31;
    int wl = threadIdx.x >> 5;
    if (gw >= node1) return;
    const int v = gw;
    const int off0 = g_off[v];
    const int deg = g_off[v + 1] - off0;
    const float4 sd = g_s1dst[v];

    float4 mx;
    mx.x = lrelu(decf(g_gmax[0]) + decf(g_gmax[4]));
    mx.y = lrelu(decf(g_gmax[1]) + decf(g_gmax[5]));
    mx.z = lrelu(decf(g_gmax[2]) + decf(g_gmax[6]));
    mx.w = lrelu(decf(g_gmax[3]) + decf(g_gmax[7]));

    float4 dn = make_float4(0.f, 0.f, 0.f, 0.f);
    float a[8];
#pragma unroll
    for (int j = 0; j < 8; j++) a[j] = 0.f;
    const int hsel = lane >> 3;
    const uint4* whb = (const uint4*)g_Wh1f;

    for (int base = 0; base < deg; base += 32) {
        int j = base + lane;
        float4 w4 = make_float4(0.f, 0.f, 0.f, 0.f);
        int s = 0;
        if (j < deg) {
            s = g_eid[off0 + j];
            float4 ss = g_s1src[s];
            w4.x = __expf(lrelu(ss.x + sd.x) - mx.x);
            w4.y = __expf(lrelu(ss.y + sd.y) - mx.y);
            w4.z = __expf(lrelu(ss.z + sd.z) - mx.z);
            w4.w = __expf(lrelu(ss.w + sd.w) - mx.w);
            dn.x += w4.x; dn.y += w4.y; dn.z += w4.z; dn.w += w4.w;
        }
        sw[wl][lane] = w4;
        ssm[wl][lane] = s;
        __syncwarp();
        int cnt = min(32, deg - base);
#pragma unroll 4
        for (int k = 0; k < cnt; k++) {
            int sk = ssm[wl][k];
            float wk = ((const float*)(sw[wl] + k))[hsel];
            uint4 rv = whb[(size_t)sk * 32 + lane];
            const __half2* hp = (const __half2*)&rv;
            float2 f0 = __half22float2(hp[0]);
            float2 f1 = __half22float2(hp[1]);
            float2 f2 = __half22float2(hp[2]);
            float2 f3 = __half22float2(hp[3]);
            a[0] += wk * f0.x; a[1] += wk * f0.y;
            a[2] += wk * f1.x; a[3] += wk * f1.y;
            a[4] += wk * f2.x; a[5] += wk * f2.y;
            a[6] += wk * f3.x; a[7] += wk * f3.y;
        }
        __syncwarp();
    }

    dn.x = wredsum(dn.x); dn.y = wredsum(dn.y);
    dn.z = wredsum(dn.z); dn.w = wredsum(dn.w);
    float invs[4];
    invs[0] = (deg > 0) ? 1.f / dn.x : 0.f;
    invs[1] = (deg > 0) ? 1.f / dn.y : 0.f;
    invs[2] = (deg > 0) ? 1.f / dn.z : 0.f;
    invs[3] = (deg > 0) ? 1.f / dn.w : 0.f;
    float invh = invs[hsel];

    __half hh[8];
#pragma unroll
    for (int j = 0; j < 8; j++) {
        float vv = a[j] * invh;
        vv = vv > 0.f ? vv : expm1f(vv);
        hh[j] = __float2half_rn(vv);
    }
    *(uint4*)(g_Xf + (size_t)v * 256 + lane * 8) = *(uint4*)hh;
}

// ---------------- layer-2 aggregation + log_softmax: fp16 gather ----------------
__global__ void agg2_kernel(float* __restrict__ out) {
    int gw = blockIdx.x * 8 + (threadIdx.x >> 5);
    int lane = threadIdx.x & 31;
    if (gw >= N_NODES) return;
    const int v = gw;
    const int off0 = g_off[v];
    const int deg = g_off[v + 1] - off0;
    const float sd = g_s2dst[v];
    const float mx = lrelu(decf(g_gmax[8]) + decf(g_gmax[9]));
    const bool valid = lane < 20;

    float dn = 0.f;
    float ax = 0.f, ay = 0.f;
    for (int base = 0; base < deg; base += 32) {
        int j = base + lane;
        float w = 0.f;
        int s = 0;
        if (j < deg) {
            s = g_eid[off0 + j];
            w = __expf(lrelu(g_s2src[s] + sd) - mx);
            dn += w;
        }
        int cnt = min(32, deg - base);
#pragma unroll 4
        for (int k = 0; k < cnt; k++) {
            int sk = __shfl_sync(FULLMASK, s, k);
            float wk = __shfl_sync(FULLMASK, w, k);
            if (valid) {
                __half2 hv = *((const __half2*)(g_Wh2f + (size_t)sk * 40) + lane);
                float2 f = __half22float2(hv);
                ax += wk * f.x;
                ay += wk * f.y;
            }
        }
    }
    dn = wredsum(dn);
    float inv = (deg > 0) ? 1.f / dn : 0.f;
    ax *= inv;
    ay *= inv;

    float m = wredmax(valid ? fmaxf(ax, ay) : -3e38f);
    float se = wredsum(valid ? (__expf(ax - m) + __expf(ay - m)) : 0.f);
    float lse = m + logf(se);
    if (valid) {
        out[(size_t)v * NCLASS + 2 * lane] = ax - lse;
        out[(size_t)v * NCLASS + 2 * lane + 1] = ay - lse;
    }
}

// ---------------- launcher ----------------
extern "C" void kernel_launch(void* const* d_in, const int* in_sizes, int n_in,
                              void* d_out, int out_size) {
    const float* h = (const float*)d_in[0];
    const int* ei = (const int*)d_in[1];
    const float* Wheads = (const float*)d_in[2];
    const float* aheads = (const float*)d_in[3];
    const float* Wout = (const float*)d_in[4];
    const float* aout = (const float*)d_in[5];
    const int* src = ei;
    const int* dst = ei + N_EDGES;
    float* out = (float*)d_out;

    __half *pW1h, *pW1l, *pW2f, *pWh1f, *pXf, *pWh2f;
    cudaGetSymbolAddress((void**)&pW1h, g_W1t_hi);
    cudaGetSymbolAddress((void**)&pW1l, g_W1t_lo);
    cudaGetSymbolAddress((void**)&pW2f, g_W2f);
    cudaGetSymbolAddress((void**)&pWh1f, g_Wh1f);
    cudaGetSymbolAddress((void**)&pXf, g_Xf);
    cudaGetSymbolAddress((void**)&pWh2f, g_Wh2f);

    constexpr int SMEM1 = 23552 + 4 * (256 * 40 * 2);             // 105472
    constexpr int SMEM2 = 2 * (128 * 40 * 2) + 2 * (64 * 40 * 2); // 30720

    cudaFuncSetAttribute((const void*)gemm1_kernel,
                         cudaFuncAttributeMaxDynamicSharedMemorySize, SMEM1);
    cudaFuncSetAttribute((const void*)gemm2_kernel,
                         cudaFuncAttributeMaxDynamicSharedMemorySize, SMEM2);

    // side stream + events (capture-time handles; graph keeps parallel branches)
    cudaStream_t s2;
    cudaStreamCreateWithFlags(&s2, cudaStreamNonBlocking);
    cudaEvent_t evF, evJ, evG;
    cudaEventCreateWithFlags(&evF, cudaEventDisableTiming);
    cudaEventCreateWithFlags(&evJ, cudaEventDisableTiming);
    cudaEventCreateWithFlags(&evG, cudaEventDisableTiming);
    cudaEvent_t evA[4];
    for (int c = 0; c < 4; c++) cudaEventCreateWithFlags(&evA[c], cudaEventDisableTiming);

    setup_kernel<<<(N_NODES + 256) / 256, 256>>>(Wheads, Wout);

    // fork: CSR chain on s2, concurrent with GEMM1 on the main stream
    cudaEventRecord(evF, cudaStreamPerThread);
    cudaStreamWaitEvent(s2, evF, 0);
    count_kernel<<<N_EDGES / 256, 256, 0, s2>>>(dst);
    {
        int n = N_NODES + 1;
        int nb = (n + 1023) / 1024;  // 98
        scan1_kernel<<<nb, 1024, 0, s2>>>(n);
        scan2_kernel<<<1, 128, 0, s2>>>(nb);
        scan3_kernel<<<(n + 255) / 256, 256, 0, s2>>>(n);
    }
    fill_kernel<<<N_EDGES / 256, 256, 0, s2>>>(dst, src);
    cudaEventRecord(evJ, s2);

    gemm1_kernel<<<dim3(1, (N_NODES + 63) / 64), 256, SMEM1>>>(
        h, pW1h, pW1l, pWh1f, aheads, N_NODES);

    // join: agg1 needs both CSR and GEMM1 results
    cudaStreamWaitEvent(cudaStreamPerThread, evJ, 0);

    // pipelined agg1 (main) -> gemm2 (s2) in 4 node chunks
    const int bounds[5] = {0, 25088, 50176, 75264, N_NODES};
    for (int c = 0; c < 4; c++) {
        int n0 = bounds[c], n1 = bounds[c + 1];
        int sz = n1 - n0;
        agg1_kernel<<<(sz + 7) / 8, 256>>>(n0, n1);
        cudaEventRecord(evA[c], cudaStreamPerThread);
        cudaStreamWaitEvent(s2, evA[c], 0);
        gemm2_kernel<<<dim3(1, (sz + 127) / 128), 256, SMEM2, s2>>>(
            pXf, pW2f, pWh2f, aout, n0, n1);
    }
    cudaEventRecord(evG, s2);
    cudaStreamWaitEvent(cudaStreamPerThread, evG, 0);

    agg2_kernel<<<(N_NODES + 7) / 8, 256>>>(out);
}

// round 10
// speedup vs baseline: 1.0882x; 1.0882x over previous
#include <cuda_runtime.h>
#include <cuda_bf16.h>
#include <cuda_fp16.h>
#include <math.h>
#include <stdint.h>

#define N_NODES 100000
#define N_EDGES 1600000
#define NCLASS  40
#define LALPHA  0.2f
#define FULLMASK 0xffffffffu

// ---------------- scratch (static device globals) ----------------
__device__ __align__(16) __half g_W1t_hi[256 * 256];           // Wcat^T fp16 hi
__device__ __align__(16) __half g_W1t_lo[256 * 256];           // Wcat^T fp16 lo (residual)
__device__ __align__(16) __half g_W2f[64 * 256];               // W_out^T padded, fp16
__device__ __align__(16) __half g_Wh1f[(size_t)N_NODES * 256]; // layer1 features fp16
__device__ __align__(16) __half g_Xf[(size_t)N_NODES * 256];   // layer1 output fp16
__device__ __align__(16) __half g_Wh2f[(size_t)N_NODES * 40];  // layer2 logits fp16, stride 40
__device__ float4 g_s1src[N_NODES];
__device__ float4 g_s1dst[N_NODES];
__device__ float g_s2src[N_NODES];
__device__ float g_s2dst[N_NODES];
__device__ int g_deg[N_NODES + 1];
__device__ int g_off[N_NODES + 1];
__device__ int g_rank[N_EDGES];
__device__ int g_eid[N_EDGES];
__device__ int g_bsum[128];
__device__ int g_bsum2[128];
__device__ unsigned g_gmax[10];

// ---------------- helpers ----------------
__device__ __forceinline__ float wredmax(float v) {
#pragma unroll
    for (int o = 16; o; o >>= 1) v = fmaxf(v, __shfl_xor_sync(FULLMASK, v, o));
    return v;
}
__device__ __forceinline__ float wredsum(float v) {
#pragma unroll
    for (int o = 16; o; o >>= 1) v += __shfl_xor_sync(FULLMASK, v, o);
    return v;
}
__device__ __forceinline__ float lrelu(float x) { return x > 0.f ? x : LALPHA * x; }
__device__ __forceinline__ unsigned encf(float f) {
    int i = __float_as_int(f);
    return (i < 0) ? ~(unsigned)i : ((unsigned)i | 0x80000000u);
}
__device__ __forceinline__ float decf(unsigned u) {
    int i = (u & 0x80000000u) ? (int)(u & 0x7fffffffu) : ~(int)u;
    return __int_as_float(i);
}
__device__ __forceinline__ void mma_f16(float* c, const unsigned* a, const unsigned* b) {
    asm volatile(
        "mma.sync.aligned.m16n8k16.row.col.f32.f16.f16.f32 "
        "{%0,%1,%2,%3},{%4,%5,%6,%7},{%8,%9},{%0,%1,%2,%3};"
        : "+f"(c[0]), "+f"(c[1]), "+f"(c[2]), "+f"(c[3])
        : "r"(a[0]), "r"(a[1]), "r"(a[2]), "r"(a[3]), "r"(b[0]), "r"(b[1]));
}
__device__ __forceinline__ void ldsm_x4(unsigned* r, unsigned a) {
    asm volatile("ldmatrix.sync.aligned.m8n8.x4.shared.b16 {%0,%1,%2,%3}, [%4];"
                 : "=r"(r[0]), "=r"(r[1]), "=r"(r[2]), "=r"(r[3]) : "r"(a));
}
__device__ __forceinline__ void cp16(unsigned d, const void* s, int sz) {
    asm volatile("cp.async.cg.shared.global [%0], [%1], 16, %2;" :: "r"(d), "l"(s), "r"(sz));
}
__device__ __forceinline__ void cp_commit() { asm volatile("cp.async.commit_group;"); }
template <int NW> __device__ __forceinline__ void cp_wait() {
    asm volatile("cp.async.wait_group %0;" :: "n"(NW));
}

// ---------------- merged setup: pack W1 fp16 hi/lo, pack W2, zero deg/gmax ----------------
__global__ void setup_kernel(const float* __restrict__ Wh, const float* __restrict__ Wo) {
    int idx = blockIdx.x * blockDim.x + threadIdx.x;
    if (idx <= N_NODES) g_deg[idx] = 0;
    if (idx < 10) g_gmax[idx] = encf(-3e38f);
    if (idx < 256 * 256) {
        int c = idx >> 8, k = idx & 255;
        int head = c >> 6, j = c & 63;
        float v = Wh[head * (256 * 64) + k * 64 + j];
        __half hi = __float2half_rn(v);
        g_W1t_hi[c * 256 + k] = hi;
        g_W1t_lo[c * 256 + k] = __float2half_rn(v - __half2float(hi));
    }
    if (idx < 64 * 256) {
        int c = idx >> 8, k = idx & 255;
        float v = (c < NCLASS) ? Wo[k * NCLASS + c] : 0.f;
        g_W2f[c * 256 + k] = __float2half_rn(v);
    }
}

// ---------------- GEMM1: Wh1 = h @ Wcat, A fp32 staged -> fp16 in-kernel; 2-term fp16 mma ----
__global__ __launch_bounds__(256, 2) void gemm1_kernel(
    const float* __restrict__ A,
    const __half* __restrict__ Bth, const __half* __restrict__ Btl,
    __half* __restrict__ Whf, const float* __restrict__ a_heads, int M) {
    constexpr int MI = 4, NI = 4;
    constexpr int LDSB = 40;
    constexpr int LDSAF = 36;
    constexpr int SZAF = 64 * LDSAF * 4;
    constexpr int OFF_AH = 2 * SZAF;
    constexpr int OFF_B = OFF_AH + 64 * LDSB * 2;
    constexpr int SZB = 256 * LDSB * 2;

    extern __shared__ char smem[];
    const unsigned uS = (unsigned)__cvta_generic_to_shared(smem);
    const unsigned uAf = uS;
    const unsigned uAh = uS + OFF_AH;
    const unsigned uBh = uS + OFF_B;
    const unsigned uBl = uS + OFF_B + 2 * SZB;
    float* sP = (float*)smem;
    float* sQ = (float*)(smem + 2048);
    float* sMp = (float*)(smem + 4096);
    float* sMq = (float*)(smem + 4224);

    const int tid = threadIdx.x, lane = tid & 31, wid = tid >> 5;
    const int wn = wid;
    const int brow = blockIdx.y * 64;

    float acc[MI][NI][4];
#pragma unroll
    for (int mi = 0; mi < MI; mi++)
#pragma unroll
        for (int ni = 0; ni < NI; ni++)
#pragma unroll
            for (int q = 0; q < 4; q++) acc[mi][ni][q] = 0.f;

    auto stage = [&](int s, int k0) {
#pragma unroll
        for (int it = 0; it < 2; it++) {
            int i = tid + it * 256;
            int row = i >> 3, c = i & 7;
            int gr = brow + row;
            int ok = (gr < M) ? 16 : 0;
            const float* srcp = A + (size_t)min(gr, M - 1) * 256 + k0 + c * 4;
            cp16(uAf + (unsigned)(s * SZAF + (row * LDSAF + c * 4) * 4), srcp, ok);
        }
#pragma unroll
        for (int it = 0; it < 4; it++) {
            int i = tid + it * 256;
            int row = i >> 2, c = i & 3;
            size_t go = (size_t)row * 256 + k0 + c * 8;
            unsigned dof = (unsigned)(s * SZB + (row * LDSB + c * 8) * 2);
            cp16(uBh + dof, Bth + go, 16);
            cp16(uBl + dof, Btl + go, 16);
        }
    };

    stage(0, 0);
    cp_commit();

#pragma unroll
    for (int it = 0; it < 8; it++) {
        const int s = it & 1;
        if (it < 7) {
            stage(s ^ 1, (it + 1) * 32);
            cp_commit();
            cp_wait<1>();
        } else {
            cp_wait<0>();
        }
        __syncthreads();

        {
            int row = tid >> 2, seg = tid & 3;
            const char* pf = smem + s * SZAF + (row * LDSAF + seg * 8) * 4;
            float4 v0 = *(const float4*)pf;
            float4 v1 = *(const float4*)(pf + 16);
            __half hh[8];
            hh[0] = __float2half_rn(v0.x); hh[1] = __float2half_rn(v0.y);
            hh[2] = __float2half_rn(v0.z); hh[3] = __float2half_rn(v0.w);
            hh[4] = __float2half_rn(v1.x); hh[5] = __float2half_rn(v1.y);
            hh[6] = __float2half_rn(v1.z); hh[7] = __float2half_rn(v1.w);
            *(uint4*)(smem + OFF_AH + (row * LDSB + seg * 8) * 2) = *(uint4*)hh;
        }
        __syncthreads();

#pragma unroll
        for (int kk = 0; kk < 32; kk += 16) {
            unsigned ah[MI][4], bh[NI][2], bl[NI][2];
            const int ra = lane & 15;
            const int kca = (lane >> 4) << 3;
#pragma unroll
            for (int mi = 0; mi < MI; mi++) {
                unsigned off = (unsigned)(((mi * 16 + ra) * LDSB + kk + kca) * 2);
                ldsm_x4(ah[mi], uAh + off);
            }
            const int rb = (lane & 7) + ((lane >> 4) << 3);
            const int kcb = ((lane >> 3) & 1) << 3;
#pragma unroll
            for (int nb = 0; nb < NI / 2; nb++) {
                unsigned off = (unsigned)(((wn * 32 + nb * 16 + rb) * LDSB + kk + kcb) * 2) +
                               (unsigned)(s * SZB);
                unsigned t4[4];
                ldsm_x4(t4, uBh + off);
                bh[2 * nb][0] = t4[0]; bh[2 * nb][1] = t4[1];
                bh[2 * nb + 1][0] = t4[2]; bh[2 * nb + 1][1] = t4[3];
                ldsm_x4(t4, uBl + off);
                bl[2 * nb][0] = t4[0]; bl[2 * nb][1] = t4[1];
                bl[2 * nb + 1][0] = t4[2]; bl[2 * nb + 1][1] = t4[3];
            }
#pragma unroll
            for (int mi = 0; mi < MI; mi++)
#pragma unroll
                for (int ni = 0; ni < NI; ni++) {
                    mma_f16(acc[mi][ni], ah[mi], bh[ni]);
                    mma_f16(acc[mi][ni], ah[mi], bl[ni]);
                }
        }
        __syncthreads();
    }

    // epilogue: fused scores + fp16 store
    const int g = lane >> 2, t = lane & 3;
    float asr[NI][2], adr[NI][2];
#pragma unroll
    for (int ni = 0; ni < NI; ni++)
#pragma unroll
        for (int qq = 0; qq < 2; qq++) {
            int cl = wn * 32 + ni * 8 + 2 * t + qq;
            asr[ni][qq] = a_heads[(cl >> 6) * 128 + (cl & 63)];
            adr[ni][qq] = a_heads[(cl >> 6) * 128 + 64 + (cl & 63)];
        }
#pragma unroll
    for (int mi = 0; mi < MI; mi++) {
        float p0 = 0.f, q0 = 0.f, p1 = 0.f, q1 = 0.f;
#pragma unroll
        for (int ni = 0; ni < NI; ni++)
#pragma unroll
            for (int qq = 0; qq < 2; qq++) {
                p0 += acc[mi][ni][qq] * asr[ni][qq];
                q0 += acc[mi][ni][qq] * adr[ni][qq];
                p1 += acc[mi][ni][2 + qq] * asr[ni][qq];
                q1 += acc[mi][ni][2 + qq] * adr[ni][qq];
            }
#pragma unroll
        for (int o = 1; o <= 2; o <<= 1) {
            p0 += __shfl_xor_sync(FULLMASK, p0, o);
            q0 += __shfl_xor_sync(FULLMASK, q0, o);
            p1 += __shfl_xor_sync(FULLMASK, p1, o);
            q1 += __shfl_xor_sync(FULLMASK, q1, o);
        }
        int r0 = mi * 16 + g;
        if (t == 0) {
            sP[r0 * 8 + wn] = p0; sQ[r0 * 8 + wn] = q0;
            sP[(r0 + 8) * 8 + wn] = p1; sQ[(r0 + 8) * 8 + wn] = q1;
        }
        int gr0 = brow + r0;
#pragma unroll
        for (int ni = 0; ni < NI; ni++) {
            int c = wn * 32 + ni * 8 + 2 * t;
            if (gr0 < M)
                *(__half2*)(Whf + (size_t)gr0 * 256 + c) =
                    __floats2half2_rn(acc[mi][ni][0], acc[mi][ni][1]);
            if (gr0 + 8 < M)
                *(__half2*)(Whf + (size_t)(gr0 + 8) * 256 + c) =
                    __floats2half2_rn(acc[mi][ni][2], acc[mi][ni][3]);
        }
    }
    __syncthreads();
    {
        int row = tid >> 2, hd = tid & 3;
        int gr = brow + row;
        float p = -3e38f, q = -3e38f;
        float pv = sP[row * 8 + 2 * hd] + sP[row * 8 + 2 * hd + 1];
        float qv = sQ[row * 8 + 2 * hd] + sQ[row * 8 + 2 * hd + 1];
        if (gr < M) {
            ((float*)g_s1src)[gr * 4 + hd] = pv;
            ((float*)g_s1dst)[gr * 4 + hd] = qv;
            p = pv; q = qv;
        }
#pragma unroll
        for (int o = 4; o <= 16; o <<= 1) {
            p = fmaxf(p, __shfl_xor_sync(FULLMASK, p, o));
            q = fmaxf(q, __shfl_xor_sync(FULLMASK, q, o));
        }
        if (lane < 4) {
            sMp[wid * 4 + lane] = p;
            sMq[wid * 4 + lane] = q;
        }
    }
    __syncthreads();
    if (tid < 32) {
        int h = tid & 3;
        float p = sMp[tid], q = sMq[tid];
#pragma unroll
        for (int o = 4; o <= 16; o <<= 1) {
            p = fmaxf(p, __shfl_xor_sync(FULLMASK, p, o));
            q = fmaxf(q, __shfl_xor_sync(FULLMASK, q, o));
        }
        if (tid < 4) {
            atomicMax(&g_gmax[h], encf(p));
            atomicMax(&g_gmax[4 + h], encf(q));
        }
    }
}

// ---------------- GEMM2: Wh2 = x @ W2 (fp16 1-term) + fused scores2 + max ----------------
__global__ __launch_bounds__(256, 2) void gemm2_kernel(
    const __half* __restrict__ A, const __half* __restrict__ Bt,
    __half* __restrict__ Whf, const float* __restrict__ a_out, int M) {
    constexpr int WM = 64, WN = 16, MI = 4, NI = 2, WNW = 4;
    constexpr int LDSB = 40;
    constexpr int SZA = 128 * LDSB * 2;
    constexpr int SZB = 64 * LDSB * 2;

    extern __shared__ char smem[];
    const unsigned uA = (unsigned)__cvta_generic_to_shared(smem);
    const unsigned uB = uA + 2 * SZA;
    __shared__ float sAS[64], sAD[64];
    __shared__ float sP[128][4], sQ[128][4];
    __shared__ float sMp[8], sMq[8];

    const int tid = threadIdx.x, lane = tid & 31, wid = tid >> 5;
    const int wm = wid / WNW, wn = wid % WNW;
    const int brow = blockIdx.y * 128;

    if (tid < 64) {
        sAS[tid] = (tid < NCLASS) ? a_out[tid] : 0.f;
        sAD[tid] = (tid < NCLASS) ? a_out[NCLASS + tid] : 0.f;
    }

    float acc[MI][NI][4];
#pragma unroll
    for (int mi = 0; mi < MI; mi++)
#pragma unroll
        for (int ni = 0; ni < NI; ni++)
#pragma unroll
            for (int q = 0; q < 4; q++) acc[mi][ni][q] = 0.f;

    auto stage = [&](int s, int k0) {
#pragma unroll
        for (int i = tid; i < 512; i += 256) {
            int row = i >> 2, c = i & 3;
            int gr = brow + row;
            int ok = (gr < M) ? 16 : 0;
            size_t go = (size_t)min(gr, M - 1) * 256 + k0 + c * 8;
            cp16(uA + (unsigned)(s * SZA + (row * LDSB + c * 8) * 2), A + go, ok);
        }
        if (tid < 256) {
            int row = tid >> 2, c = tid & 3;
            size_t go = (size_t)row * 256 + k0 + c * 8;
            cp16(uB + (unsigned)(s * SZB + (row * LDSB + c * 8) * 2), Bt + go, 16);
        }
    };

    stage(0, 0);
    cp_commit();

#pragma unroll
    for (int it = 0; it < 8; it++) {
        const int s = it & 1;
        if (it < 7) {
            stage(s ^ 1, (it + 1) * 32);
            cp_commit();
            cp_wait<1>();
        } else {
            cp_wait<0>();
        }
        __syncthreads();

#pragma unroll
        for (int kk = 0; kk < 32; kk += 16) {
            unsigned af[MI][4], bf[NI][2];
            const int ra = lane & 15;
            const int kca = (lane >> 4) << 3;
#pragma unroll
            for (int mi = 0; mi < MI; mi++) {
                unsigned off = (unsigned)(((wm * WM + mi * 16 + ra) * LDSB + kk + kca) * 2) +
                               (unsigned)(s * SZA);
                ldsm_x4(af[mi], uA + off);
            }
            const int rb = (lane & 7) + ((lane >> 4) << 3);
            const int kcb = ((lane >> 3) & 1) << 3;
            {
                unsigned off = (unsigned)(((wn * WN + rb) * LDSB + kk + kcb) * 2) +
                               (unsigned)(s * SZB);
                unsigned t4[4];
                ldsm_x4(t4, uB + off);
                bf[0][0] = t4[0]; bf[0][1] = t4[1];
                bf[1][0] = t4[2]; bf[1][1] = t4[3];
            }
#pragma unroll
            for (int mi = 0; mi < MI; mi++)
#pragma unroll
                for (int ni = 0; ni < NI; ni++)
                    mma_f16(acc[mi][ni], af[mi], bf[ni]);
        }
        __syncthreads();
    }

    const int g = lane >> 2, t = lane & 3;
#pragma unroll
    for (int mi = 0; mi < MI; mi++) {
        float p0 = 0.f, q0 = 0.f, p1 = 0.f, q1 = 0.f;
#pragma unroll
        for (int ni = 0; ni < NI; ni++)
#pragma unroll
            for (int qq = 0; qq < 2; qq++) {
                int cl = wn * WN + ni * 8 + 2 * t + qq;
                float as = sAS[cl], ad = sAD[cl];
                p0 += acc[mi][ni][qq] * as;
                q0 += acc[mi][ni][qq] * ad;
                p1 += acc[mi][ni][2 + qq] * as;
                q1 += acc[mi][ni][2 + qq] * ad;
            }
#pragma unroll
        for (int o = 1; o <= 2; o <<= 1) {
            p0 += __shfl_xor_sync(FULLMASK, p0, o);
            q0 += __shfl_xor_sync(FULLMASK, q0, o);
            p1 += __shfl_xor_sync(FULLMASK, p1, o);
            q1 += __shfl_xor_sync(FULLMASK, q1, o);
        }
        int r0 = wm * WM + mi * 16 + g;
        if (t == 0) {
            sP[r0][wn] = p0; sQ[r0][wn] = q0;
            sP[r0 + 8][wn] = p1; sQ[r0 + 8][wn] = q1;
        }
        int gr0 = brow + r0;
#pragma unroll
        for (int ni = 0; ni < NI; ni++) {
            int c = wn * WN + ni * 8 + 2 * t;
            if (c < NCLASS) {
                if (gr0 < M)
                    *(__half2*)(Whf + (size_t)gr0 * 40 + c) =
                        __floats2half2_rn(acc[mi][ni][0], acc[mi][ni][1]);
                if (gr0 + 8 < M)
                    *(__half2*)(Whf + (size_t)(gr0 + 8) * 40 + c) =
                        __floats2half2_rn(acc[mi][ni][2], acc[mi][ni][3]);
            }
        }
    }
    __syncthreads();
    {
        float p = -3e38f, q = -3e38f;
        if (tid < 128) {
            int gr = brow + tid;
            float pv = sP[tid][0] + sP[tid][1] + sP[tid][2] + sP[tid][3];
            float qv = sQ[tid][0] + sQ[tid][1] + sQ[tid][2] + sQ[tid][3];
            if (gr < M) {
                g_s2src[gr] = pv;
                g_s2dst[gr] = qv;
                p = pv; q = qv;
            }
        }
        p = wredmax(p);
        q = wredmax(q);
        if (lane == 0) {
            sMp[wid] = p;
            sMq[wid] = q;
        }
    }
    __syncthreads();
    if (tid == 0) {
        float p = sMp[0], q = sMq[0];
#pragma unroll
        for (int w = 1; w < 8; w++) {
            p = fmaxf(p, sMp[w]);
            q = fmaxf(q, sMq[w]);
        }
        atomicMax(&g_gmax[8], encf(p));
        atomicMax(&g_gmax[9], encf(q));
    }
}

// ---------------- CSR build (single-atomic: count stores rank) ----------------
__global__ void count_kernel(const int* __restrict__ dst) {
    int e = blockIdx.x * blockDim.x + threadIdx.x;
    if (e < N_EDGES) g_rank[e] = atomicAdd(&g_deg[dst[e]], 1);
}
__global__ void scan1_kernel(int n) {
    __shared__ int s[1024];
    int tid = threadIdx.x;
    int gid = blockIdx.x * 1024 + tid;
    int v = (gid < n) ? g_deg[gid] : 0;
    s[tid] = v;
    __syncthreads();
    int t = v;
    for (int d = 1; d < 1024; d <<= 1) {
        int add = (tid >= d) ? s[tid - d] : 0;
        __syncthreads();
        t += add;
        s[tid] = t;
        __syncthreads();
    }
    if (gid < n) g_off[gid] = t - v;
    if (tid == 1023) g_bsum[blockIdx.x] = t;
}
__global__ void scan2_kernel(int nb) {
    __shared__ int s[128];
    int tid = threadIdx.x;
    int v = (tid < nb) ? g_bsum[tid] : 0;
    s[tid] = v;
    __syncthreads();
    int t = v;
    for (int d = 1; d < 128; d <<= 1) {
        int add = (tid >= d) ? s[tid - d] : 0;
        __syncthreads();
        t += add;
        s[tid] = t;
        __syncthreads();
    }
    if (tid < nb) g_bsum2[tid] = t - v;
}
__global__ void scan3_kernel(int n) {
    int i = blockIdx.x * blockDim.x + threadIdx.x;
    if (i < n) g_off[i] += g_bsum2[i >> 10];
}
__global__ void fill_kernel(const int* __restrict__ dst, const int* __restrict__ src) {
    int e = blockIdx.x * blockDim.x + threadIdx.x;
    if (e >= N_EDGES) return;
    int pos = g_off[dst[e]] + g_rank[e];
    g_eid[pos] = src[e];
}

// ---------------- layer-1 aggregation: fp16 gather, single pass ----------------
__global__ void agg1_kernel() {
    __shared__ float4 sw[8][32];
    __shared__ int ssm[8][32];
    int gw = blockIdx.x * 8 + (threadIdx.x >> 5);
    int lane = threadIdx.x & 31;
    int wl = threadIdx.x >> 5;
    if (gw >= N_NODES) return;
    const int v = gw;
    const int off0 = g_off[v];
    const int deg = g_off[v + 1] - off0;
    const float4 sd = g_s1dst[v];

    float4 mx;
    mx.x = lrelu(decf(g_gmax[0]) + decf(g_gmax[4]));
    mx.y = lrelu(decf(g_gmax[1]) + decf(g_gmax[5]));
    mx.z = lrelu(decf(g_gmax[2]) + decf(g_gmax[6]));
    mx.w = lrelu(decf(g_gmax[3]) + decf(g_gmax[7]));

    float4 dn = make_float4(0.f, 0.f, 0.f, 0.f);
    float a[8];
#pragma unroll
    for (int j = 0; j < 8; j++) a[j] = 0.f;
    const int hsel = lane >> 3;
    const uint4* whb = (const uint4*)g_Wh1f;

    for (int base = 0; base < deg; base += 32) {
        int j = base + lane;
        float4 w4 = make_float4(0.f, 0.f, 0.f, 0.f);
        int s = 0;
        if (j < deg) {
            s = g_eid[off0 + j];
            float4 ss = g_s1src[s];
            w4.x = __expf(lrelu(ss.x + sd.x) - mx.x);
            w4.y = __expf(lrelu(ss.y + sd.y) - mx.y);
            w4.z = __expf(lrelu(ss.z + sd.z) - mx.z);
            w4.w = __expf(lrelu(ss.w + sd.w) - mx.w);
            dn.x += w4.x; dn.y += w4.y; dn.z += w4.z; dn.w += w4.w;
        }
        sw[wl][lane] = w4;
        ssm[wl][lane] = s;
        __syncwarp();
        int cnt = min(32, deg - base);
        for (int k = 0; k < cnt; k++) {
            int sk = ssm[wl][k];
            float wk = ((const float*)(sw[wl] + k))[hsel];
            uint4 rv = whb[(size_t)sk * 32 + lane];
            const __half2* hp = (const __half2*)&rv;
            float2 f0 = __half22float2(hp[0]);
            float2 f1 = __half22float2(hp[1]);
            float2 f2 = __half22float2(hp[2]);
            float2 f3 = __half22float2(hp[3]);
            a[0] += wk * f0.x; a[1] += wk * f0.y;
            a[2] += wk * f1.x; a[3] += wk * f1.y;
            a[4] += wk * f2.x; a[5] += wk * f2.y;
            a[6] += wk * f3.x; a[7] += wk * f3.y;
        }
        __syncwarp();
    }

    dn.x = wredsum(dn.x); dn.y = wredsum(dn.y);
    dn.z = wredsum(dn.z); dn.w = wredsum(dn.w);
    float invs[4];
    invs[0] = (deg > 0) ? 1.f / dn.x : 0.f;
    invs[1] = (deg > 0) ? 1.f / dn.y : 0.f;
    invs[2] = (deg > 0) ? 1.f / dn.z : 0.f;
    invs[3] = (deg > 0) ? 1.f / dn.w : 0.f;
    float invh = invs[hsel];

    __half hh[8];
#pragma unroll
    for (int j = 0; j < 8; j++) {
        float vv = a[j] * invh;
        vv = vv > 0.f ? vv : expm1f(vv);
        hh[j] = __float2half_rn(vv);
    }
    *(uint4*)(g_Xf + (size_t)v * 256 + lane * 8) = *(uint4*)hh;
}

// ---------------- layer-2 aggregation + log_softmax: fp16 gather (unroll 4) ----------------
__global__ void agg2_kernel(float* __restrict__ out) {
    int gw = blockIdx.x * 8 + (threadIdx.x >> 5);
    int lane = threadIdx.x & 31;
    if (gw >= N_NODES) return;
    const int v = gw;
    const int off0 = g_off[v];
    const int deg = g_off[v + 1] - off0;
    const float sd = g_s2dst[v];
    const float mx = lrelu(decf(g_gmax[8]) + decf(g_gmax[9]));
    const bool valid = lane < 20;

    float dn = 0.f;
    float ax = 0.f, ay = 0.f;
    for (int base = 0; base < deg; base += 32) {
        int j = base + lane;
        float w = 0.f;
        int s = 0;
        if (j < deg) {
            s = g_eid[off0 + j];
            w = __expf(lrelu(g_s2src[s] + sd) - mx);
            dn += w;
        }
        int cnt = min(32, deg - base);
#pragma unroll 4
        for (int k = 0; k < cnt; k++) {
            int sk = __shfl_sync(FULLMASK, s, k);
            float wk = __shfl_sync(FULLMASK, w, k);
            if (valid) {
                __half2 hv = *((const __half2*)(g_Wh2f + (size_t)sk * 40) + lane);
                float2 f = __half22float2(hv);
                ax += wk * f.x;
                ay += wk * f.y;
            }
        }
    }
    dn = wredsum(dn);
    float inv = (deg > 0) ? 1.f / dn : 0.f;
    ax *= inv;
    ay *= inv;

    float m = wredmax(valid ? fmaxf(ax, ay) : -3e38f);
    float se = wredsum(valid ? (__expf(ax - m) + __expf(ay - m)) : 0.f);
    float lse = m + logf(se);
    if (valid) {
        out[(size_t)v * NCLASS + 2 * lane] = ax - lse;
        out[(size_t)v * NCLASS + 2 * lane + 1] = ay - lse;
    }
}

// ---------------- launcher ----------------
extern "C" void kernel_launch(void* const* d_in, const int* in_sizes, int n_in,
                              void* d_out, int out_size) {
    const float* h = (const float*)d_in[0];
    const int* ei = (const int*)d_in[1];
    const float* Wheads = (const float*)d_in[2];
    const float* aheads = (const float*)d_in[3];
    const float* Wout = (const float*)d_in[4];
    const float* aout = (const float*)d_in[5];
    const int* src = ei;
    const int* dst = ei + N_EDGES;
    float* out = (float*)d_out;

    __half *pW1h, *pW1l, *pW2f, *pWh1f, *pXf, *pWh2f;
    cudaGetSymbolAddress((void**)&pW1h, g_W1t_hi);
    cudaGetSymbolAddress((void**)&pW1l, g_W1t_lo);
    cudaGetSymbolAddress((void**)&pW2f, g_W2f);
    cudaGetSymbolAddress((void**)&pWh1f, g_Wh1f);
    cudaGetSymbolAddress((void**)&pXf, g_Xf);
    cudaGetSymbolAddress((void**)&pWh2f, g_Wh2f);

    constexpr int SMEM1 = 23552 + 4 * (256 * 40 * 2);             // 105472
    constexpr int SMEM2 = 2 * (128 * 40 * 2) + 2 * (64 * 40 * 2); // 30720

    cudaFuncSetAttribute((const void*)gemm1_kernel,
                         cudaFuncAttributeMaxDynamicSharedMemorySize, SMEM1);
    cudaFuncSetAttribute((const void*)gemm2_kernel,
                         cudaFuncAttributeMaxDynamicSharedMemorySize, SMEM2);

    // side stream + fork/join events (capture-time handles; graph keeps parallel branches)
    cudaStream_t s2;
    cudaStreamCreateWithFlags(&s2, cudaStreamNonBlocking);
    cudaEvent_t evF, evJ;
    cudaEventCreateWithFlags(&evF, cudaEventDisableTiming);
    cudaEventCreateWithFlags(&evJ, cudaEventDisableTiming);

    setup_kernel<<<(N_NODES + 256) / 256, 256>>>(Wheads, Wout);

    // fork: CSR chain on s2, concurrent with GEMM1 on the main stream
    cudaEventRecord(evF, cudaStreamPerThread);
    cudaStreamWaitEvent(s2, evF, 0);
    count_kernel<<<N_EDGES / 256, 256, 0, s2>>>(dst);
    {
        int n = N_NODES + 1;
        int nb = (n + 1023) / 1024;  // 98
        scan1_kernel<<<nb, 1024, 0, s2>>>(n);
        scan2_kernel<<<1, 128, 0, s2>>>(nb);
        scan3_kernel<<<(n + 255) / 256, 256, 0, s2>>>(n);
    }
    fill_kernel<<<N_EDGES / 256, 256, 0, s2>>>(dst, src);
    cudaEventRecord(evJ, s2);

    gemm1_kernel<<<dim3(1, (N_NODES + 63) / 64), 256, SMEM1>>>(
        h, pW1h, pW1l, pWh1f, aheads, N_NODES);

    // join: agg1 needs both CSR and GEMM1 results
    cudaStreamWaitEvent(cudaStreamPerThread, evJ, 0);

    agg1_kernel<<<(N_NODES + 7) / 8, 256>>>();

    gemm2_kernel<<<dim3(1, (N_NODES + 127) / 128), 256, SMEM2>>>(
        pXf, pW2f, pWh2f, aout, N_NODES);

    agg2_kernel<<<(N_NODES + 7) / 8, 256>>>(out);
}

// round 11
// speedup vs baseline: 1.2009x; 1.1036x over previous
#include <cuda_runtime.h>
#include <cuda_bf16.h>
#include <cuda_fp16.h>
#include <math.h>
#include <stdint.h>

#define N_NODES 100000
#define N_EDGES 1600000
#define NCLASS  40
#define LALPHA  0.2f
#define FULLMASK 0xffffffffu

// ---------------- scratch (static device globals) ----------------
__device__ __align__(16) __half g_W1t[256 * 256];              // Wcat^T fp16
__device__ __align__(16) __half g_W2f[64 * 256];               // W_out^T padded, fp16
__device__ __align__(16) __half g_Wh1f[(size_t)N_NODES * 256]; // layer1 features fp16
__device__ __align__(16) __half g_Xf[(size_t)N_NODES * 256];   // layer1 output fp16
__device__ __align__(16) __half g_Wh2f[(size_t)N_NODES * 40];  // layer2 logits fp16, stride 40
__device__ float4 g_s1src[N_NODES];
__device__ float4 g_s1dst[N_NODES];
__device__ float g_s2src[N_NODES];
__device__ float g_s2dst[N_NODES];
__device__ int g_deg[N_NODES + 1];
__device__ int g_off[N_NODES + 1];
__device__ int g_rank[N_EDGES];
__device__ int g_eid[N_EDGES];
__device__ int g_bsum[128];
__device__ int g_bsum2[128];
__device__ unsigned g_gmax[10];

// ---------------- helpers ----------------
__device__ __forceinline__ float wredmax(float v) {
#pragma unroll
    for (int o = 16; o; o >>= 1) v = fmaxf(v, __shfl_xor_sync(FULLMASK, v, o));
    return v;
}
__device__ __forceinline__ float wredsum(float v) {
#pragma unroll
    for (int o = 16; o; o >>= 1) v += __shfl_xor_sync(FULLMASK, v, o);
    return v;
}
__device__ __forceinline__ float lrelu(float x) { return x > 0.f ? x : LALPHA * x; }
__device__ __forceinline__ unsigned encf(float f) {
    int i = __float_as_int(f);
    return (i < 0) ? ~(unsigned)i : ((unsigned)i | 0x80000000u);
}
__device__ __forceinline__ float decf(unsigned u) {
    int i = (u & 0x80000000u) ? (int)(u & 0x7fffffffu) : ~(int)u;
    return __int_as_float(i);
}
__device__ __forceinline__ void mma_f16(float* c, const unsigned* a, const unsigned* b) {
    asm volatile(
        "mma.sync.aligned.m16n8k16.row.col.f32.f16.f16.f32 "
        "{%0,%1,%2,%3},{%4,%5,%6,%7},{%8,%9},{%0,%1,%2,%3};"
        : "+f"(c[0]), "+f"(c[1]), "+f"(c[2]), "+f"(c[3])
        : "r"(a[0]), "r"(a[1]), "r"(a[2]), "r"(a[3]), "r"(b[0]), "r"(b[1]));
}
__device__ __forceinline__ void ldsm_x4(unsigned* r, unsigned a) {
    asm volatile("ldmatrix.sync.aligned.m8n8.x4.shared.b16 {%0,%1,%2,%3}, [%4];"
                 : "=r"(r[0]), "=r"(r[1]), "=r"(r[2]), "=r"(r[3]) : "r"(a));
}
__device__ __forceinline__ void cp16(unsigned d, const void* s, int sz) {
    asm volatile("cp.async.cg.shared.global [%0], [%1], 16, %2;" :: "r"(d), "l"(s), "r"(sz));
}
__device__ __forceinline__ void cp_commit() { asm volatile("cp.async.commit_group;"); }
template <int NW> __device__ __forceinline__ void cp_wait() {
    asm volatile("cp.async.wait_group %0;" :: "n"(NW));
}

// ---------------- merged setup: pack W1 fp16, pack W2, zero deg/gmax ----------------
__global__ void setup_kernel(const float* __restrict__ Wh, const float* __restrict__ Wo) {
    int idx = blockIdx.x * blockDim.x + threadIdx.x;
    if (idx <= N_NODES) g_deg[idx] = 0;
    if (idx < 10) g_gmax[idx] = encf(-3e38f);
    if (idx < 256 * 256) {
        int c = idx >> 8, k = idx & 255;
        int head = c >> 6, j = c & 63;
        float v = Wh[head * (256 * 64) + k * 64 + j];
        g_W1t[c * 256 + k] = __float2half_rn(v);
    }
    if (idx < 64 * 256) {
        int c = idx >> 8, k = idx & 255;
        float v = (c < NCLASS) ? Wo[k * NCLASS + c] : 0.f;
        g_W2f[c * 256 + k] = __float2half_rn(v);
    }
}

// ---------------- GEMM1: Wh1 = h @ Wcat, A fp32 staged -> fp16 in-kernel; 1-term fp16 mma ----
// BM=64, BN=256, 256 threads, warp grid 1x8 (WM=64, WN=32).
// Fused: scores1 + global max atomics. Epilogue reuses A-f32 smem.
__global__ __launch_bounds__(256, 2) void gemm1_kernel(
    const float* __restrict__ A, const __half* __restrict__ Bt,
    __half* __restrict__ Whf, const float* __restrict__ a_heads, int M) {
    constexpr int MI = 4, NI = 4;
    constexpr int LDSB = 40;
    constexpr int LDSAF = 36;
    constexpr int SZAF = 64 * LDSAF * 4;     // 9216 per fp32 A stage
    constexpr int OFF_AH = 2 * SZAF;         // 18432 (single fp16 A buffer)
    constexpr int OFF_B = OFF_AH + 64 * LDSB * 2;   // 23552
    constexpr int SZB = 256 * LDSB * 2;      // 20480 per B stage
    // total dynamic: 23552 + 2*20480 = 64512

    extern __shared__ char smem[];
    const unsigned uS = (unsigned)__cvta_generic_to_shared(smem);
    const unsigned uAf = uS;
    const unsigned uAh = uS + OFF_AH;
    const unsigned uB = uS + OFF_B;
    float* sP = (float*)smem;
    float* sQ = (float*)(smem + 2048);
    float* sMp = (float*)(smem + 4096);
    float* sMq = (float*)(smem + 4224);

    const int tid = threadIdx.x, lane = tid & 31, wid = tid >> 5;
    const int wn = wid;
    const int brow = blockIdx.y * 64;

    float acc[MI][NI][4];
#pragma unroll
    for (int mi = 0; mi < MI; mi++)
#pragma unroll
        for (int ni = 0; ni < NI; ni++)
#pragma unroll
            for (int q = 0; q < 4; q++) acc[mi][ni][q] = 0.f;

    auto stage = [&](int s, int k0) {
#pragma unroll
        for (int it = 0; it < 2; it++) {
            int i = tid + it * 256;
            int row = i >> 3, c = i & 7;
            int gr = brow + row;
            int ok = (gr < M) ? 16 : 0;
            const float* srcp = A + (size_t)min(gr, M - 1) * 256 + k0 + c * 4;
            cp16(uAf + (unsigned)(s * SZAF + (row * LDSAF + c * 4) * 4), srcp, ok);
        }
#pragma unroll
        for (int it = 0; it < 4; it++) {
            int i = tid + it * 256;
            int row = i >> 2, c = i & 3;
            size_t go = (size_t)row * 256 + k0 + c * 8;
            cp16(uB + (unsigned)(s * SZB + (row * LDSB + c * 8) * 2), Bt + go, 16);
        }
    };

    stage(0, 0);
    cp_commit();

#pragma unroll
    for (int it = 0; it < 8; it++) {
        const int s = it & 1;
        if (it < 7) {
            stage(s ^ 1, (it + 1) * 32);
            cp_commit();
            cp_wait<1>();
        } else {
            cp_wait<0>();
        }
        __syncthreads();

        // convert A fp32 stage s -> single fp16 buffer
        {
            int row = tid >> 2, seg = tid & 3;
            const char* pf = smem + s * SZAF + (row * LDSAF + seg * 8) * 4;
            float4 v0 = *(const float4*)pf;
            float4 v1 = *(const float4*)(pf + 16);
            __half hh[8];
            hh[0] = __float2half_rn(v0.x); hh[1] = __float2half_rn(v0.y);
            hh[2] = __float2half_rn(v0.z); hh[3] = __float2half_rn(v0.w);
            hh[4] = __float2half_rn(v1.x); hh[5] = __float2half_rn(v1.y);
            hh[6] = __float2half_rn(v1.z); hh[7] = __float2half_rn(v1.w);
            *(uint4*)(smem + OFF_AH + (row * LDSB + seg * 8) * 2) = *(uint4*)hh;
        }
        __syncthreads();

#pragma unroll
        for (int kk = 0; kk < 32; kk += 16) {
            unsigned ah[MI][4], bf[NI][2];
            const int ra = lane & 15;
            const int kca = (lane >> 4) << 3;
#pragma unroll
            for (int mi = 0; mi < MI; mi++) {
                unsigned off = (unsigned)(((mi * 16 + ra) * LDSB + kk + kca) * 2);
                ldsm_x4(ah[mi], uAh + off);
            }
            const int rb = (lane & 7) + ((lane >> 4) << 3);
            const int kcb = ((lane >> 3) & 1) << 3;
#pragma unroll
            for (int nb = 0; nb < NI / 2; nb++) {
                unsigned off = (unsigned)(((wn * 32 + nb * 16 + rb) * LDSB + kk + kcb) * 2) +
                               (unsigned)(s * SZB);
                unsigned t4[4];
                ldsm_x4(t4, uB + off);
                bf[2 * nb][0] = t4[0]; bf[2 * nb][1] = t4[1];
                bf[2 * nb + 1][0] = t4[2]; bf[2 * nb + 1][1] = t4[3];
            }
#pragma unroll
            for (int mi = 0; mi < MI; mi++)
#pragma unroll
                for (int ni = 0; ni < NI; ni++)
                    mma_f16(acc[mi][ni], ah[mi], bf[ni]);
        }
        __syncthreads();
    }

    // epilogue: fused scores + fp16 store (a_heads read direct; L1-resident)
    const int g = lane >> 2, t = lane & 3;
    float asr[NI][2], adr[NI][2];
#pragma unroll
    for (int ni = 0; ni < NI; ni++)
#pragma unroll
        for (int qq = 0; qq < 2; qq++) {
            int cl = wn * 32 + ni * 8 + 2 * t + qq;
            asr[ni][qq] = a_heads[(cl >> 6) * 128 + (cl & 63)];
            adr[ni][qq] = a_heads[(cl >> 6) * 128 + 64 + (cl & 63)];
        }
#pragma unroll
    for (int mi = 0; mi < MI; mi++) {
        float p0 = 0.f, q0 = 0.f, p1 = 0.f, q1 = 0.f;
#pragma unroll
        for (int ni = 0; ni < NI; ni++)
#pragma unroll
            for (int qq = 0; qq < 2; qq++) {
                p0 += acc[mi][ni][qq] * asr[ni][qq];
                q0 += acc[mi][ni][qq] * adr[ni][qq];
                p1 += acc[mi][ni][2 + qq] * asr[ni][qq];
                q1 += acc[mi][ni][2 + qq] * adr[ni][qq];
            }
#pragma unroll
        for (int o = 1; o <= 2; o <<= 1) {
            p0 += __shfl_xor_sync(FULLMASK, p0, o);
            q0 += __shfl_xor_sync(FULLMASK, q0, o);
            p1 += __shfl_xor_sync(FULLMASK, p1, o);
            q1 += __shfl_xor_sync(FULLMASK, q1, o);
        }
        int r0 = mi * 16 + g;
        if (t == 0) {
            sP[r0 * 8 + wn] = p0; sQ[r0 * 8 + wn] = q0;
            sP[(r0 + 8) * 8 + wn] = p1; sQ[(r0 + 8) * 8 + wn] = q1;
        }
        int gr0 = brow + r0;
#pragma unroll
        for (int ni = 0; ni < NI; ni++) {
            int c = wn * 32 + ni * 8 + 2 * t;
            if (gr0 < M)
                *(__half2*)(Whf + (size_t)gr0 * 256 + c) =
                    __floats2half2_rn(acc[mi][ni][0], acc[mi][ni][1]);
            if (gr0 + 8 < M)
                *(__half2*)(Whf + (size_t)(gr0 + 8) * 256 + c) =
                    __floats2half2_rn(acc[mi][ni][2], acc[mi][ni][3]);
        }
    }
    __syncthreads();
    {
        int row = tid >> 2, hd = tid & 3;
        int gr = brow + row;
        float p = -3e38f, q = -3e38f;
        float pv = sP[row * 8 + 2 * hd] + sP[row * 8 + 2 * hd + 1];
        float qv = sQ[row * 8 + 2 * hd] + sQ[row * 8 + 2 * hd + 1];
        if (gr < M) {
            ((float*)g_s1src)[gr * 4 + hd] = pv;
            ((float*)g_s1dst)[gr * 4 + hd] = qv;
            p = pv; q = qv;
        }
#pragma unroll
        for (int o = 4; o <= 16; o <<= 1) {
            p = fmaxf(p, __shfl_xor_sync(FULLMASK, p, o));
            q = fmaxf(q, __shfl_xor_sync(FULLMASK, q, o));
        }
        if (lane < 4) {
            sMp[wid * 4 + lane] = p;
            sMq[wid * 4 + lane] = q;
        }
    }
    __syncthreads();
    if (tid < 32) {
        int h = tid & 3;
        float p = sMp[tid], q = sMq[tid];
#pragma unroll
        for (int o = 4; o <= 16; o <<= 1) {
            p = fmaxf(p, __shfl_xor_sync(FULLMASK, p, o));
            q = fmaxf(q, __shfl_xor_sync(FULLMASK, q, o));
        }
        if (tid < 4) {
            atomicMax(&g_gmax[h], encf(p));
            atomicMax(&g_gmax[4 + h], encf(q));
        }
    }
}

// ---------------- GEMM2: Wh2 = x @ W2 (fp16 1-term) + fused scores2 + max ----------------
__global__ __launch_bounds__(256, 2) void gemm2_kernel(
    const __half* __restrict__ A, const __half* __restrict__ Bt,
    __half* __restrict__ Whf, const float* __restrict__ a_out, int M) {
    constexpr int WM = 64, WN = 16, MI = 4, NI = 2, WNW = 4;
    constexpr int LDSB = 40;
    constexpr int SZA = 128 * LDSB * 2;
    constexpr int SZB = 64 * LDSB * 2;

    extern __shared__ char smem[];
    const unsigned uA = (unsigned)__cvta_generic_to_shared(smem);
    const unsigned uB = uA + 2 * SZA;
    __shared__ float sAS[64], sAD[64];
    __shared__ float sP[128][4], sQ[128][4];
    __shared__ float sMp[8], sMq[8];

    const int tid = threadIdx.x, lane = tid & 31, wid = tid >> 5;
    const int wm = wid / WNW, wn = wid % WNW;
    const int brow = blockIdx.y * 128;

    if (tid < 64) {
        sAS[tid] = (tid < NCLASS) ? a_out[tid] : 0.f;
        sAD[tid] = (tid < NCLASS) ? a_out[NCLASS + tid] : 0.f;
    }

    float acc[MI][NI][4];
#pragma unroll
    for (int mi = 0; mi < MI; mi++)
#pragma unroll
        for (int ni = 0; ni < NI; ni++)
#pragma unroll
            for (int q = 0; q < 4; q++) acc[mi][ni][q] = 0.f;

    auto stage = [&](int s, int k0) {
#pragma unroll
        for (int i = tid; i < 512; i += 256) {
            int row = i >> 2, c = i & 3;
            int gr = brow + row;
            int ok = (gr < M) ? 16 : 0;
            size_t go = (size_t)min(gr, M - 1) * 256 + k0 + c * 8;
            cp16(uA + (unsigned)(s * SZA + (row * LDSB + c * 8) * 2), A + go, ok);
        }
        if (tid < 256) {
            int row = tid >> 2, c = tid & 3;
            size_t go = (size_t)row * 256 + k0 + c * 8;
            cp16(uB + (unsigned)(s * SZB + (row * LDSB + c * 8) * 2), Bt + go, 16);
        }
    };

    stage(0, 0);
    cp_commit();

#pragma unroll
    for (int it = 0; it < 8; it++) {
        const int s = it & 1;
        if (it < 7) {
            stage(s ^ 1, (it + 1) * 32);
            cp_commit();
            cp_wait<1>();
        } else {
            cp_wait<0>();
        }
        __syncthreads();

#pragma unroll
        for (int kk = 0; kk < 32; kk += 16) {
            unsigned af[MI][4], bf[NI][2];
            const int ra = lane & 15;
            const int kca = (lane >> 4) << 3;
#pragma unroll
            for (int mi = 0; mi < MI; mi++) {
                unsigned off = (unsigned)(((wm * WM + mi * 16 + ra) * LDSB + kk + kca) * 2) +
                               (unsigned)(s * SZA);
                ldsm_x4(af[mi], uA + off);
            }
            const int rb = (lane & 7) + ((lane >> 4) << 3);
            const int kcb = ((lane >> 3) & 1) << 3;
            {
                unsigned off = (unsigned)(((wn * WN + rb) * LDSB + kk + kcb) * 2) +
                               (unsigned)(s * SZB);
                unsigned t4[4];
                ldsm_x4(t4, uB + off);
                bf[0][0] = t4[0]; bf[0][1] = t4[1];
                bf[1][0] = t4[2]; bf[1][1] = t4[3];
            }
#pragma unroll
            for (int mi = 0; mi < MI; mi++)
#pragma unroll
                for (int ni = 0; ni < NI; ni++)
                    mma_f16(acc[mi][ni], af[mi], bf[ni]);
        }
        __syncthreads();
    }

    const int g = lane >> 2, t = lane & 3;
#pragma unroll
    for (int mi = 0; mi < MI; mi++) {
        float p0 = 0.f, q0 = 0.f, p1 = 0.f, q1 = 0.f;
#pragma unroll
        for (int ni = 0; ni < NI; ni++)
#pragma unroll
            for (int qq = 0; qq < 2; qq++) {
                int cl = wn * WN + ni * 8 + 2 * t + qq;
                float as = sAS[cl], ad = sAD[cl];
                p0 += acc[mi][ni][qq] * as;
                q0 += acc[mi][ni][qq] * ad;
                p1 += acc[mi][ni][2 + qq] * as;
                q1 += acc[mi][ni][2 + qq] * ad;
            }
#pragma unroll
        for (int o = 1; o <= 2; o <<= 1) {
            p0 += __shfl_xor_sync(FULLMASK, p0, o);
            q0 += __shfl_xor_sync(FULLMASK, q0, o);
            p1 += __shfl_xor_sync(FULLMASK, p1, o);
            q1 += __shfl_xor_sync(FULLMASK, q1, o);
        }
        int r0 = wm * WM + mi * 16 + g;
        if (t == 0) {
            sP[r0][wn] = p0; sQ[r0][wn] = q0;
            sP[r0 + 8][wn] = p1; sQ[r0 + 8][wn] = q1;
        }
        int gr0 = brow + r0;
#pragma unroll
        for (int ni = 0; ni < NI; ni++) {
            int c = wn * WN + ni * 8 + 2 * t;
            if (c < NCLASS) {
                if (gr0 < M)
                    *(__half2*)(Whf + (size_t)gr0 * 40 + c) =
                        __floats2half2_rn(acc[mi][ni][0], acc[mi][ni][1]);
                if (gr0 + 8 < M)
                    *(__half2*)(Whf + (size_t)(gr0 + 8) * 40 + c) =
                        __floats2half2_rn(acc[mi][ni][2], acc[mi][ni][3]);
            }
        }
    }
    __syncthreads();
    {
        float p = -3e38f, q = -3e38f;
        if (tid < 128) {
            int gr = brow + tid;
            float pv = sP[tid][0] + sP[tid][1] + sP[tid][2] + sP[tid][3];
            float qv = sQ[tid][0] + sQ[tid][1] + sQ[tid][2] + sQ[tid][3];
            if (gr < M) {
                g_s2src[gr] = pv;
                g_s2dst[gr] = qv;
                p = pv; q = qv;
            }
        }
        p = wredmax(p);
        q = wredmax(q);
        if (lane == 0) {
            sMp[wid] = p;
            sMq[wid] = q;
        }
    }
    __syncthreads();
    if (tid == 0) {
        float p = sMp[0], q = sMq[0];
#pragma unroll
        for (int w = 1; w < 8; w++) {
            p = fmaxf(p, sMp[w]);
            q = fmaxf(q, sMq[w]);
        }
        atomicMax(&g_gmax[8], encf(p));
        atomicMax(&g_gmax[9], encf(q));
    }
}

// ---------------- CSR build (single-atomic: count stores rank) ----------------
__global__ void count_kernel(const int* __restrict__ dst) {
    int e = blockIdx.x * blockDim.x + threadIdx.x;
    if (e < N_EDGES) g_rank[e] = atomicAdd(&g_deg[dst[e]], 1);
}
__global__ void scan1_kernel(int n) {
    __shared__ int s[1024];
    int tid = threadIdx.x;
    int gid = blockIdx.x * 1024 + tid;
    int v = (gid < n) ? g_deg[gid] : 0;
    s[tid] = v;
    __syncthreads();
    int t = v;
    for (int d = 1; d < 1024; d <<= 1) {
        int add = (tid >= d) ? s[tid - d] : 0;
        __syncthreads();
        t += add;
        s[tid] = t;
        __syncthreads();
    }
    if (gid < n) g_off[gid] = t - v;
    if (tid == 1023) g_bsum[blockIdx.x] = t;
}
__global__ void scan2_kernel(int nb) {
    __shared__ int s[128];
    int tid = threadIdx.x;
    int v = (tid < nb) ? g_bsum[tid] : 0;
    s[tid] = v;
    __syncthreads();
    int t = v;
    for (int d = 1; d < 128; d <<= 1) {
        int add = (tid >= d) ? s[tid - d] : 0;
        __syncthreads();
        t += add;
        s[tid] = t;
        __syncthreads();
    }
    if (tid < nb) g_bsum2[tid] = t - v;
}
__global__ void scan3_kernel(int n) {
    int i = blockIdx.x * blockDim.x + threadIdx.x;
    if (i < n) g_off[i] += g_bsum2[i >> 10];
}
__global__ void fill_kernel(const int* __restrict__ dst, const int* __restrict__ src) {
    int e = blockIdx.x * blockDim.x + threadIdx.x;
    if (e >= N_EDGES) return;
    int pos = g_off[dst[e]] + g_rank[e];
    g_eid[pos] = src[e];
}

// ---------------- layer-1 aggregation: fp16 gather, single pass ----------------
__global__ void agg1_kernel() {
    __shared__ float4 sw[8][32];
    __shared__ int ssm[8][32];
    int gw = blockIdx.x * 8 + (threadIdx.x >> 5);
    int lane = threadIdx.x & 31;
    int wl = threadIdx.x >> 5;
    if (gw >= N_NODES) return;
    const int v = gw;
    const int off0 = g_off[v];
    const int deg = g_off[v + 1] - off0;
    const float4 sd = g_s1dst[v];

    float4 mx;
    mx.x = lrelu(decf(g_gmax[0]) + decf(g_gmax[4]));
    mx.y = lrelu(decf(g_gmax[1]) + decf(g_gmax[5]));
    mx.z = lrelu(decf(g_gmax[2]) + decf(g_gmax[6]));
    mx.w = lrelu(decf(g_gmax[3]) + decf(g_gmax[7]));

    float4 dn = make_float4(0.f, 0.f, 0.f, 0.f);
    float a[8];
#pragma unroll
    for (int j = 0; j < 8; j++) a[j] = 0.f;
    const int hsel = lane >> 3;
    const uint4* whb = (const uint4*)g_Wh1f;

    for (int base = 0; base < deg; base += 32) {
        int j = base + lane;
        float4 w4 = make_float4(0.f, 0.f, 0.f, 0.f);
        int s = 0;
        if (j < deg) {
            s = g_eid[off0 + j];
            float4 ss = g_s1src[s];
            w4.x = __expf(lrelu(ss.x + sd.x) - mx.x);
            w4.y = __expf(lrelu(ss.y + sd.y) - mx.y);
            w4.z = __expf(lrelu(ss.z + sd.z) - mx.z);
            w4.w = __expf(lrelu(ss.w + sd.w) - mx.w);
            dn.x += w4.x; dn.y += w4.y; dn.z += w4.z; dn.w += w4.w;
        }
        sw[wl][lane] = w4;
        ssm[wl][lane] = s;
        __syncwarp();
        int cnt = min(32, deg - base);
        for (int k = 0; k < cnt; k++) {
            int sk = ssm[wl][k];
            float wk = ((const float*)(sw[wl] + k))[hsel];
            uint4 rv = whb[(size_t)sk * 32 + lane];
            const __half2* hp = (const __half2*)&rv;
            float2 f0 = __half22float2(hp[0]);
            float2 f1 = __half22float2(hp[1]);
            float2 f2 = __half22float2(hp[2]);
            float2 f3 = __half22float2(hp[3]);
            a[0] += wk * f0.x; a[1] += wk * f0.y;
            a[2] += wk * f1.x; a[3] += wk * f1.y;
            a[4] += wk * f2.x; a[5] += wk * f2.y;
            a[6] += wk * f3.x; a[7] += wk * f3.y;
        }
        __syncwarp();
    }

    dn.x = wredsum(dn.x); dn.y = wredsum(dn.y);
    dn.z = wredsum(dn.z); dn.w = wredsum(dn.w);
    float invs[4];
    invs[0] = (deg > 0) ? 1.f / dn.x : 0.f;
    invs[1] = (deg > 0) ? 1.f / dn.y : 0.f;
    invs[2] = (deg > 0) ? 1.f / dn.z : 0.f;
    invs[3] = (deg > 0) ? 1.f / dn.w : 0.f;
    float invh = invs[hsel];

    __half hh[8];
#pragma unroll
    for (int j = 0; j < 8; j++) {
        float vv = a[j] * invh;
        vv = vv > 0.f ? vv : expm1f(vv);
        hh[j] = __float2half_rn(vv);
    }
    *(uint4*)(g_Xf + (size_t)v * 256 + lane * 8) = *(uint4*)hh;
}

// ---------------- layer-2 aggregation + log_softmax: fp16 gather ----------------
__global__ void agg2_kernel(float* __restrict__ out) {
    int gw = blockIdx.x * 8 + (threadIdx.x >> 5);
    int lane = threadIdx.x & 31;
    if (gw >= N_NODES) return;
    const int v = gw;
    const int off0 = g_off[v];
    const int deg = g_off[v + 1] - off0;
    const float sd = g_s2dst[v];
    const float mx = lrelu(decf(g_gmax[8]) + decf(g_gmax[9]));
    const bool valid = lane < 20;

    float dn = 0.f;
    float ax = 0.f, ay = 0.f;
    for (int base = 0; base < deg; base += 32) {
        int j = base + lane;
        float w = 0.f;
        int s = 0;
        if (j < deg) {
            s = g_eid[off0 + j];
            w = __expf(lrelu(g_s2src[s] + sd) - mx);
            dn += w;
        }
        int cnt = min(32, deg - base);
#pragma unroll 4
        for (int k = 0; k < cnt; k++) {
            int sk = __shfl_sync(FULLMASK, s, k);
            float wk = __shfl_sync(FULLMASK, w, k);
            if (valid) {
                __half2 hv = *((const __half2*)(g_Wh2f + (size_t)sk * 40) + lane);
                float2 f = __half22float2(hv);
                ax += wk * f.x;
                ay += wk * f.y;
            }
        }
    }
    dn = wredsum(dn);
    float inv = (deg > 0) ? 1.f / dn : 0.f;
    ax *= inv;
    ay *= inv;

    float m = wredmax(valid ? fmaxf(ax, ay) : -3e38f);
    float se = wredsum(valid ? (__expf(ax - m) + __expf(ay - m)) : 0.f);
    float lse = m + logf(se);
    if (valid) {
        out[(size_t)v * NCLASS + 2 * lane] = ax - lse;
        out[(size_t)v * NCLASS + 2 * lane + 1] = ay - lse;
    }
}

// ---------------- launcher ----------------
extern "C" void kernel_launch(void* const* d_in, const int* in_sizes, int n_in,
                              void* d_out, int out_size) {
    const float* h = (const float*)d_in[0];
    const int* ei = (const int*)d_in[1];
    const float* Wheads = (const float*)d_in[2];
    const float* aheads = (const float*)d_in[3];
    const float* Wout = (const float*)d_in[4];
    const float* aout = (const float*)d_in[5];
    const int* src = ei;
    const int* dst = ei + N_EDGES;
    float* out = (float*)d_out;

    __half *pW1t, *pW2f, *pWh1f, *pXf, *pWh2f;
    cudaGetSymbolAddress((void**)&pW1t, g_W1t);
    cudaGetSymbolAddress((void**)&pW2f, g_W2f);
    cudaGetSymbolAddress((void**)&pWh1f, g_Wh1f);
    cudaGetSymbolAddress((void**)&pXf, g_Xf);
    cudaGetSymbolAddress((void**)&pWh2f, g_Wh2f);

    constexpr int SMEM1 = 23552 + 2 * (256 * 40 * 2);             // 64512
    constexpr int SMEM2 = 2 * (128 * 40 * 2) + 2 * (64 * 40 * 2); // 30720

    cudaFuncSetAttribute((const void*)gemm1_kernel,
                         cudaFuncAttributeMaxDynamicSharedMemorySize, SMEM1);
    cudaFuncSetAttribute((const void*)gemm2_kernel,
                         cudaFuncAttributeMaxDynamicSharedMemorySize, SMEM2);

    // side stream + fork/join events (capture-time handles; graph keeps parallel branches)
    cudaStream_t s2;
    cudaStreamCreateWithFlags(&s2, cudaStreamNonBlocking);
    cudaEvent_t evF, evJ;
    cudaEventCreateWithFlags(&evF, cudaEventDisableTiming);
    cudaEventCreateWithFlags(&evJ, cudaEventDisableTiming);

    setup_kernel<<<(N_NODES + 256) / 256, 256>>>(Wheads, Wout);

    // fork: CSR chain on s2, concurrent with GEMM1 on the main stream
    cudaEventRecord(evF, cudaStreamPerThread);
    cudaStreamWaitEvent(s2, evF, 0);
    count_kernel<<<N_EDGES / 256, 256, 0, s2>>>(dst);
    {
        int n = N_NODES + 1;
        int nb = (n + 1023) / 1024;  // 98
        scan1_kernel<<<nb, 1024, 0, s2>>>(n);
        scan2_kernel<<<1, 128, 0, s2>>>(nb);
        scan3_kernel<<<(n + 255) / 256, 256, 0, s2>>>(n);
    }
    fill_kernel<<<N_EDGES / 256, 256, 0, s2>>>(dst, src);
    cudaEventRecord(evJ, s2);

    gemm1_kernel<<<dim3(1, (N_NODES + 63) / 64), 256, SMEM1>>>(
        h, pW1t, pWh1f, aheads, N_NODES);

    // join: agg1 needs both CSR and GEMM1 results
    cudaStreamWaitEvent(cudaStreamPerThread, evJ, 0);

    agg1_kernel<<<(N_NODES + 7) / 8, 256>>>();

    gemm2_kernel<<<dim3(1, (N_NODES + 127) / 128), 256, SMEM2>>>(
        pXf, pW2f, pWh2f, aout, N_NODES);

    agg2_kernel<<<(N_NODES + 7) / 8, 256>>>(out);
}